// round 1
// baseline (speedup 1.0000x reference)
#include <cuda_runtime.h>
#include <math.h>

#define BATCH 4
#define LSEQ  512
#define DMODEL 512
#define DFF   512
#define DINNER 256
#define NST   16
#define MR    (BATCH*LSEQ)   /* 2048 rows */

// ---------------------------------------------------------------------------
// Scratch: single static device buffer (allocation-free rule)
// ---------------------------------------------------------------------------
__device__ __align__(16) float g_scratch[20u*1024u*1024u];  // 80 MB

__device__ __forceinline__ float siluf(float x){ return x / (1.0f + expf(-x)); }
__device__ __forceinline__ float softplusf(float x){ return (x > 20.0f) ? x : log1pf(expf(x)); }

// ---------------------------------------------------------------------------
// Generic fp32 GEMM: C[M,N] = act(A[M,K](lda) @ W[K,N](ldw) + bias)
// 64x64 tile, 256 threads, 4x4 microtile, K-chunk 16.
// Requires: M % 64 == 0, K % 16 == 0 (true for all call sites). N arbitrary.
// Batched via blockIdx.z with element strides Ab/Wb/Cb.
// ---------------------------------------------------------------------------
template<int ACT>
__global__ __launch_bounds__(256)
void gemm_k(const float* __restrict__ A, const float* __restrict__ W,
            const float* __restrict__ bias, float* __restrict__ C,
            int M, int N, int K, int lda, int ldw, int ldc,
            long long Ab, long long Wb, long long Cb)
{
    __shared__ __align__(16) float As[16][68];
    __shared__ __align__(16) float Bs[16][64];
    const int bz = blockIdx.z;
    A += (long long)bz * Ab;  W += (long long)bz * Wb;  C += (long long)bz * Cb;
    const int t  = threadIdx.x;
    const int tx = t & 15, ty = t >> 4;
    const int row0 = blockIdx.y * 64, col0 = blockIdx.x * 64;
    const int a_k = (t & 3) * 4, a_r = t >> 2;     // A: 64 rows x 16 k, float4 per thread
    const int b_n = (t & 15) * 4, b_k = t >> 4;    // W: 16 k x 64 n, float4 per thread
    float acc[4][4] = {};

    for (int kb = 0; kb < K; kb += 16) {
        float4 av = *(const float4*)(A + (long long)(row0 + a_r) * lda + kb + a_k);
        float4 bv;
        {
            int gn = col0 + b_n;
            const float* wp = W + (long long)(kb + b_k) * ldw + gn;
            if (gn + 3 < N) bv = *(const float4*)wp;
            else {
                bv.x = (gn+0<N) ? wp[0] : 0.f;
                bv.y = (gn+1<N) ? wp[1] : 0.f;
                bv.z = (gn+2<N) ? wp[2] : 0.f;
                bv.w = (gn+3<N) ? wp[3] : 0.f;
            }
        }
        __syncthreads();
        As[a_k  ][a_r] = av.x;
        As[a_k+1][a_r] = av.y;
        As[a_k+2][a_r] = av.z;
        As[a_k+3][a_r] = av.w;
        *(float4*)&Bs[b_k][b_n] = bv;
        __syncthreads();
        #pragma unroll
        for (int kk = 0; kk < 16; kk++) {
            float4 a4 = *(const float4*)&As[kk][ty*4];
            float4 b4 = *(const float4*)&Bs[kk][tx*4];
            float ar[4] = {a4.x, a4.y, a4.z, a4.w};
            float br[4] = {b4.x, b4.y, b4.z, b4.w};
            #pragma unroll
            for (int i=0;i<4;i++)
                #pragma unroll
                for (int j=0;j<4;j++)
                    acc[i][j] = fmaf(ar[i], br[j], acc[i][j]);
        }
    }
    #pragma unroll
    for (int i=0;i<4;i++) {
        int gr = row0 + ty*4 + i;
        #pragma unroll
        for (int j=0;j<4;j++) {
            int gn = col0 + tx*4 + j;
            if (gn < N) {
                float c = acc[i][j];
                if (bias) c += bias[gn];
                if (ACT==1) c = siluf(c);
                if (ACT==2) c = softplusf(c);
                C[(long long)gr*ldc + gn] = c;
            }
        }
    }
}

// ---------------------------------------------------------------------------
// hs0(2048x1024) -> sx=silu(x-half), sz=silu(z-half),
// fx = silu(flip_L(sx)), fz = silu(flip_L(sz))
// ---------------------------------------------------------------------------
__global__ void silu_flip_k(const float* __restrict__ hs0, float* __restrict__ sx,
                            float* __restrict__ sz, float* __restrict__ fx,
                            float* __restrict__ fz)
{
    int i = blockIdx.x*256 + threadIdx.x;
    if (i >= MR*DFF) return;
    int d = i & (DFF-1);
    int m = i >> 9;
    int b = m >> 9, tt = m & (LSEQ-1);
    float s1 = siluf(hs0[m*1024 + d]);
    float s2 = siluf(hs0[m*1024 + 512 + d]);
    sx[i] = s1; sz[i] = s2;
    int mf = (b << 9) + (LSEQ-1 - tt);
    fx[mf*DFF + d] = siluf(s1);
    fz[mf*DFF + d] = siluf(s2);
}

// ---------------------------------------------------------------------------
// Selective scan: thread per (b,d,n). 16-lane segments reduce over states.
// h_t = exp(delta_t * A_n) * h_{t-1} + delta_t * u_t * B_{t,n};  hsum = sum_n h
// ---------------------------------------------------------------------------
__global__ void scan_k(const float* __restrict__ delta, const float* __restrict__ u,
                       const float* __restrict__ Bm, int ldb,
                       const float* __restrict__ Alog,
                       float* __restrict__ hsum, int D)
{
    int tid = blockIdx.x*256 + threadIdx.x;
    int n = tid & 15;
    int seg = tid >> 4;
    int d = seg % D;
    int b = seg / D;
    if (b >= BATCH) return;
    float An = -expf(Alog[n]);
    float h = 0.f;
    int base = b * LSEQ;
    #pragma unroll 4
    for (int ts = 0; ts < LSEQ; ts++) {
        int r = base + ts;
        float dl = delta[r*D + d];
        float ul = u[r*D + d];
        float Bv = Bm[(long long)r*ldb + n];
        float a = expf(dl * An);
        h = fmaf(a, h, dl * ul * Bv);
        float v = h;
        v += __shfl_xor_sync(0xffffffffu, v, 1);
        v += __shfl_xor_sync(0xffffffffu, v, 2);
        v += __shfl_xor_sync(0xffffffffu, v, 4);
        v += __shfl_xor_sync(0xffffffffu, v, 8);
        if (n == 0) hsum[r*D + d] = v;
    }
}

// ---------------------------------------------------------------------------
// attn[b,i,j] = softmax_j( dot(q[b,i,:], k[b,j,:]) / 16 ).  Block per (i,b).
// ---------------------------------------------------------------------------
__global__ void attn_k(const float* __restrict__ q, const float* __restrict__ k,
                       float* __restrict__ attn)
{
    const int i = blockIdx.x, b = blockIdx.y;
    __shared__ float qs[16];
    __shared__ float red[16];
    const int t = threadIdx.x;  // 256
    if (t < 16) qs[t] = q[(b*LSEQ + i)*16 + t];
    __syncthreads();
    float v[2];
    #pragma unroll
    for (int jj = 0; jj < 2; jj++) {
        int j = t + jj*256;
        const float4* kr = (const float4*)(k + (long long)(b*LSEQ + j)*16);
        float4 k0 = kr[0], k1 = kr[1], k2 = kr[2], k3 = kr[3];
        float s = qs[0]*k0.x + qs[1]*k0.y + qs[2]*k0.z + qs[3]*k0.w
                + qs[4]*k1.x + qs[5]*k1.y + qs[6]*k1.z + qs[7]*k1.w
                + qs[8]*k2.x + qs[9]*k2.y + qs[10]*k2.z + qs[11]*k2.w
                + qs[12]*k3.x + qs[13]*k3.y + qs[14]*k3.z + qs[15]*k3.w;
        v[jj] = s * (1.0f/16.0f);
    }
    float m = fmaxf(v[0], v[1]);
    for (int o=16;o;o>>=1) m = fmaxf(m, __shfl_xor_sync(0xffffffffu, m, o));
    if ((t&31)==0) red[t>>5] = m;
    __syncthreads();
    if (t == 0) { float mm = red[0]; for (int w=1;w<8;w++) mm = fmaxf(mm, red[w]); red[0] = mm; }
    __syncthreads();
    float bm = red[0];
    v[0] = expf(v[0]-bm); v[1] = expf(v[1]-bm);
    float s = v[0] + v[1];
    for (int o=16;o;o>>=1) s += __shfl_xor_sync(0xffffffffu, s, o);
    if ((t&31)==0) red[8 + (t>>5)] = s;
    __syncthreads();
    if (t == 0) { float ss = 0.f; for (int w=0;w<8;w++) ss += red[8+w]; red[8] = ss; }
    __syncthreads();
    float inv = 1.0f / red[8];
    float* arow = attn + ((long long)b*LSEQ + i)*LSEQ;
    arow[t]     = v[0]*inv;
    arow[t+256] = v[1]*inv;
}

// y[m, d] += Dm[m, d] * u[m, d]  (Dm is a slice of dbcd at column 64)
__global__ void addmul_k(float* __restrict__ y, int ldy, const float* __restrict__ dbcd,
                         int ldp, const float* __restrict__ u, int D)
{
    int i = blockIdx.x*256 + threadIdx.x;
    if (i >= MR*D) return;
    int m = i / D, d = i - m*D;
    y[(long long)m*ldy + d] += dbcd[(long long)m*ldp + 64 + d] * u[i];
}

// dst[b, t, :] = src[b, L-1-t, :]
__global__ void flip_k(const float* __restrict__ src, float* __restrict__ dst, int D)
{
    int i = blockIdx.x*256 + threadIdx.x;
    if (i >= MR*D) return;
    int d = i % D; int m = i / D;
    int b = m >> 9, tt = m & (LSEQ-1);
    dst[((b<<9) + (LSEQ-1 - tt))*D + d] = src[i];
}

__global__ void addv_k(float* __restrict__ a, const float* __restrict__ b, int n)
{
    int i = blockIdx.x*256 + threadIdx.x;
    if (i < n) a[i] += b[i];
}

__global__ void silu_out_k(const float* __restrict__ x, float* __restrict__ out, int n)
{
    int i = blockIdx.x*256 + threadIdx.x;
    if (i < n) out[i] = siluf(x[i]);
}

// ---------------------------------------------------------------------------
// Host side
// ---------------------------------------------------------------------------
static inline void gemm(int act, const float* A, const float* W, const float* bias,
                        float* C, int M, int N, int K, int lda, int ldw, int ldc,
                        int bat = 1, long long Ab = 0, long long Wb = 0, long long Cb = 0)
{
    dim3 g((N + 63) / 64, M / 64, bat), b(256);
    if (act == 0)      gemm_k<0><<<g, b>>>(A, W, bias, C, M, N, K, lda, ldw, ldc, Ab, Wb, Cb);
    else if (act == 1) gemm_k<1><<<g, b>>>(A, W, bias, C, M, N, K, lda, ldw, ldc, Ab, Wb, Cb);
    else               gemm_k<2><<<g, b>>>(A, W, bias, C, M, N, K, lda, ldw, ldc, Ab, Wb, Cb);
}

// One SSM call: dbcd proj -> delta -> scan -> q,k -> softmax attn -> y = attn@hsum (+Dm*u)
static void ssm_run(const float* u, int D, const float* projw, int Np,
                    const float* dtw, const float* dtb, const float* Alog,
                    const float* qw, const float* qb, const float* kw, const float* kb,
                    bool useD, float* yout, int ldy,
                    float* dbcd, float* delta, float* hsum, float* qbuf, float* kbuf,
                    float* attn)
{
    gemm(0, u, projw, nullptr, dbcd, MR, Np, D, D, Np, Np);
    gemm(2, dbcd, dtw, dtb, delta, MR, D, 32, Np, D, D);            // softplus
    scan_k<<<(BATCH*D*16)/256, 256>>>(delta, u, dbcd + 32, Np, Alog, hsum, D);
    gemm(2, u, qw, qb, qbuf, MR, 16, D, D, 16, 16);                 // softplus
    gemm(2, dbcd + 48, kw, kb, kbuf, MR, 16, 16, Np, 16, 16);       // softplus
    attn_k<<<dim3(LSEQ, BATCH), 256>>>(qbuf, kbuf, attn);
    gemm(0, attn, hsum, nullptr, yout, LSEQ, D, LSEQ, LSEQ, D, ldy,
         BATCH, (long long)LSEQ*LSEQ, (long long)LSEQ*D, (long long)LSEQ*ldy);
    if (useD) addmul_k<<<(MR*D)/256, 256>>>(yout, ldy, dbcd, Np, u, D);
}

extern "C" void kernel_launch(void* const* d_in, const int* in_sizes, int n_in,
                              void* d_out, int out_size)
{
    (void)in_sizes; (void)n_in; (void)out_size;
    float* S = nullptr;
    cudaGetSymbolAddress((void**)&S, g_scratch);

    // scratch layout (floats)
    float* hs0   = S;               // 2048*1024
    float* sx    = hs0   + 2097152; // 2048*512
    float* sz    = sx    + 1048576;
    float* fx    = sz    + 1048576;
    float* fz    = fx    + 1048576;
    float* ub1   = fz    + 1048576; // 2048*256
    float* ub2   = ub1   + 524288;
    float* dbcd  = ub2   + 524288;  // 2048*576
    float* delta = dbcd  + 1179648; // 2048*512
    float* hsum  = delta + 1048576; // 2048*512
    float* qbuf  = hsum  + 1048576; // 2048*16
    float* kbuf  = qbuf  + 32768;
    float* attn  = kbuf  + 32768;   // 4*512*512
    float* ycat  = attn  + 1048576; // 2048*1024
    float* ybcat = ycat  + 2097152; // 2048*512
    float* cat2  = ybcat + 1048576; // 2048*1024
    float* oe    = cat2  + 2097152; // 2048*256
    float* oef   = oe    + 524288;  // 2048*256
    float* xbuf  = oef   + 524288;  // 2048*512

    // inputs (metadata order == setup_inputs dict order)
    const float* x             = (const float*)d_in[0];
    const float* in_w          = (const float*)d_in[1];
    const float* in_b          = (const float*)d_in[2];
    const float* x_proj_w      = (const float*)d_in[3];
    const float* dt_w          = (const float*)d_in[4];
    const float* dt_b          = (const float*)d_in[5];
    const float* A_log         = (const float*)d_in[6];
    const float* exit_x_w      = (const float*)d_in[7];
    const float* exit_x_b      = (const float*)d_in[8];
    const float* exit_z_w      = (const float*)d_in[9];
    const float* exit_z_b      = (const float*)d_in[10];
    const float* x_proj_exit_w = (const float*)d_in[11];
    const float* dt_exit_w     = (const float*)d_in[12];
    const float* dt_exit_b     = (const float*)d_in[13];
    const float* A_log_exit    = (const float*)d_in[14];
    const float* out_inner_w   = (const float*)d_in[15];
    const float* out_inner_b   = (const float*)d_in[16];
    const float* out_exit_w    = (const float*)d_in[17];
    const float* out_exit_b    = (const float*)d_in[18];
    const float* up_w          = (const float*)d_in[19];
    const float* up_b          = (const float*)d_in[20];
    const float* out_w         = (const float*)d_in[21];
    const float* out_b         = (const float*)d_in[22];
    const float* q_in_w        = (const float*)d_in[23];
    const float* q_in_b        = (const float*)d_in[24];
    const float* k_in_w        = (const float*)d_in[25];
    const float* k_in_b        = (const float*)d_in[26];
    const float* q_ex_w        = (const float*)d_in[27];
    const float* q_ex_b        = (const float*)d_in[28];
    const float* k_ex_w        = (const float*)d_in[29];
    const float* k_ex_b        = (const float*)d_in[30];

    const float* cur = x;
    for (int l = 0; l < 2; l++) {
        const float* in_w_l   = in_w   + (long long)l*512*1024;
        const float* in_b_l   = in_b   + l*1024;
        const float* xp_l     = x_proj_w + (long long)l*512*576;
        const float* dtw_l    = dt_w   + l*32*512;
        const float* dtb_l    = dt_b   + l*512;
        const float* Al_l     = A_log  + l*16;
        const float* exw_l    = exit_x_w + (long long)l*512*256;
        const float* exb_l    = exit_x_b + l*256;
        const float* ezw_l    = exit_z_w + (long long)l*512*256;
        const float* ezb_l    = exit_z_b + l*256;
        const float* xpe_l    = x_proj_exit_w + (long long)l*256*320;
        const float* dtew_l   = dt_exit_w + l*32*256;
        const float* dteb_l   = dt_exit_b + l*256;
        const float* Ale_l    = A_log_exit + l*16;
        const float* oiw_l    = out_inner_w + (long long)l*1024*512;
        const float* oib_l    = out_inner_b + l*512;
        const float* oew_l    = out_exit_w + (long long)l*512*256;
        const float* oeb_l    = out_exit_b + l*256;
        const float* upw_l    = up_w  + (long long)l*256*512;
        const float* upb_l    = up_b  + l*512;
        const float* ow_l     = out_w + (long long)l*1024*512;
        const float* ob_l     = out_b + l*512;
        const float* qiw_l    = q_in_w + l*512*16;
        const float* qib_l    = q_in_b + l*16;
        const float* kiw_l    = k_in_w + l*16*16;
        const float* kib_l    = k_in_b + l*16;
        const float* qew_l    = q_ex_w + l*256*16;
        const float* qeb_l    = q_ex_b + l*16;
        const float* kew_l    = k_ex_w + l*16*16;
        const float* keb_l    = k_ex_b + l*16;

        // 1. hs0 = x @ in_w + in_b   (2048 x 1024)
        gemm(0, cur, in_w_l, in_b_l, hs0, MR, 1024, 512, 512, 1024, 1024);
        // 2. activations + flipped doubles
        silu_flip_k<<<(MR*DFF)/256, 256>>>(hs0, sx, sz, fx, fz);
        // 3. backward-path inputs
        gemm(0, fx, exw_l, exb_l, ub1, MR, 256, 512, 512, 256, 256);
        gemm(0, fz, ezw_l, ezb_l, ub2, MR, 256, 512, 512, 256, 256);
        // 4. four SSM calls
        ssm_run(sx,  512, xp_l,  576, dtw_l,  dtb_l,  Al_l,  qiw_l, qib_l, kiw_l, kib_l,
                true,  ycat,        1024, dbcd, delta, hsum, qbuf, kbuf, attn);
        ssm_run(sz,  512, xp_l,  576, dtw_l,  dtb_l,  Al_l,  qiw_l, qib_l, kiw_l, kib_l,
                true,  ycat + 512,  1024, dbcd, delta, hsum, qbuf, kbuf, attn);
        ssm_run(ub1, 256, xpe_l, 320, dtew_l, dteb_l, Ale_l, qew_l, qeb_l, kew_l, keb_l,
                false, ybcat,       512,  dbcd, delta, hsum, qbuf, kbuf, attn);
        ssm_run(ub2, 256, xpe_l, 320, dtew_l, dteb_l, Ale_l, qew_l, qeb_l, kew_l, keb_l,
                false, ybcat + 256, 512,  dbcd, delta, hsum, qbuf, kbuf, attn);
        // 5. output projections
        gemm(0, ycat,  oiw_l, oib_l, cat2,       MR, 512, 1024, 1024, 512, 1024); // out_inner -> cols 0:512
        gemm(0, ybcat, oew_l, oeb_l, oe,         MR, 256, 512,  512,  256, 256);
        flip_k<<<(MR*256)/256, 256>>>(oe, oef, 256);
        gemm(0, oef,   upw_l, upb_l, cat2 + 512, MR, 512, 256,  256,  512, 1024); // up -> cols 512:1024
        // 6. residual + final projection
        addv_k<<<(MR*1024)/256, 256>>>(cat2, hs0, MR*1024);
        gemm(0, cat2, ow_l, ob_l, xbuf, MR, 512, 1024, 1024, 512, 512);
        cur = xbuf;
    }
    silu_out_k<<<(MR*DMODEL)/256, 256>>>(xbuf, (float*)d_out, MR*DMODEL);
}

// round 2
// speedup vs baseline: 1.4536x; 1.4536x over previous
#include <cuda_runtime.h>
#include <math.h>

#define BATCH 4
#define LSEQ  512
#define DMODEL 512
#define DFF   512
#define DINNER 256
#define MR    (BATCH*LSEQ)   /* 2048 rows */
#define MR2   (2*MR)         /* 4096 rows: merged pair */

// ---------------------------------------------------------------------------
// Scratch: single static device buffer (allocation-free rule).  ~104 MB.
// ---------------------------------------------------------------------------
__device__ __align__(16) float g_scratch[26u*1024u*1024u];

__device__ __forceinline__ float siluf(float x){ return x / (1.0f + expf(-x)); }
__device__ __forceinline__ float softplusf(float x){ return (x > 20.0f) ? x : log1pf(expf(x)); }

// ---------------------------------------------------------------------------
// fp32 GEMM: C[M,N] = act(A[M,K](lda) @ W[K,N](ldw) + bias) [+ C if ACC]
// 128x64 tile, 256 threads, 8x4 microtile, K-chunk 8, double-buffered smem.
// Requires: M % 128 == 0, K % 8 == 0. N arbitrary. Batched via blockIdx.z.
// ---------------------------------------------------------------------------
template<int ACT, int ACC>
__global__ __launch_bounds__(256)
void gemm_k(const float* __restrict__ A, const float* __restrict__ W,
            const float* __restrict__ bias, float* __restrict__ C,
            int M, int N, int K, int lda, int ldw, int ldc,
            long long Ab, long long Wb, long long Cb)
{
    __shared__ __align__(16) float As[2][8][132];
    __shared__ __align__(16) float Bs[2][8][64];
    const int bz = blockIdx.z;
    A += (long long)bz * Ab;  W += (long long)bz * Wb;  C += (long long)bz * Cb;
    const int t  = threadIdx.x;
    const int row0 = blockIdx.y * 128, col0 = blockIdx.x * 64;
    const int a_r = t >> 1, a_k = (t & 1) * 4;        // A: one float4 per thread
    const int b_k = t >> 5, b_n = (t & 31) * 2;       // W: one float2 per thread
    const int tx = t & 15, ty = t >> 4;               // compute: rows ty*8, cols tx*4

    float acc[8][4] = {};
    float4 av; float2 bv;

    // prefetch chunk 0
    av = *(const float4*)(A + (long long)(row0 + a_r) * lda + a_k);
    {
        int gn = col0 + b_n;
        const float* wp = W + (long long)b_k * ldw + gn;
        bv.x = (gn   < N) ? wp[0] : 0.f;
        bv.y = (gn+1 < N) ? wp[1] : 0.f;
    }

    int buf = 0;
    for (int kb = 0; kb < K; kb += 8) {
        As[buf][a_k  ][a_r] = av.x;
        As[buf][a_k+1][a_r] = av.y;
        As[buf][a_k+2][a_r] = av.z;
        As[buf][a_k+3][a_r] = av.w;
        Bs[buf][b_k][b_n  ] = bv.x;
        Bs[buf][b_k][b_n+1] = bv.y;
        __syncthreads();
        if (kb + 8 < K) {
            av = *(const float4*)(A + (long long)(row0 + a_r) * lda + (kb + 8) + a_k);
            int gn = col0 + b_n;
            const float* wp = W + (long long)(kb + 8 + b_k) * ldw + gn;
            bv.x = (gn   < N) ? wp[0] : 0.f;
            bv.y = (gn+1 < N) ? wp[1] : 0.f;
        }
        #pragma unroll
        for (int kk = 0; kk < 8; kk++) {
            float4 a0 = *(const float4*)&As[buf][kk][ty*8];
            float4 a1 = *(const float4*)&As[buf][kk][ty*8+4];
            float4 b4 = *(const float4*)&Bs[buf][kk][tx*4];
            float ar[8] = {a0.x,a0.y,a0.z,a0.w,a1.x,a1.y,a1.z,a1.w};
            float br[4] = {b4.x,b4.y,b4.z,b4.w};
            #pragma unroll
            for (int i=0;i<8;i++)
                #pragma unroll
                for (int j=0;j<4;j++)
                    acc[i][j] = fmaf(ar[i], br[j], acc[i][j]);
        }
        buf ^= 1;
    }
    #pragma unroll
    for (int i=0;i<8;i++) {
        long long gr = row0 + ty*8 + i;
        #pragma unroll
        for (int j=0;j<4;j++) {
            int gn = col0 + tx*4 + j;
            if (gn < N) {
                float c = acc[i][j];
                if (bias) c += bias[gn];
                if (ACT==1) c = siluf(c);
                if (ACT==2) c = softplusf(c);
                if (ACC) c += C[gr*ldc + gn];
                C[gr*ldc + gn] = c;
            }
        }
    }
}

// ---------------------------------------------------------------------------
// hs0(2048x1024) -> sx=silu(x-half), sz=silu(z-half) (contiguous [4096x512]),
// fx = silu(flip_L(sx)), fz = silu(flip_L(sz)) (contiguous [4096x512])
// ---------------------------------------------------------------------------
__global__ void silu_flip_k(const float* __restrict__ hs0, float* __restrict__ sx,
                            float* __restrict__ sz, float* __restrict__ fx,
                            float* __restrict__ fz)
{
    int i = blockIdx.x*256 + threadIdx.x;
    if (i >= MR*DFF) return;
    int d = i & (DFF-1);
    int m = i >> 9;
    int b = m >> 9, tt = m & (LSEQ-1);
    float s1 = siluf(hs0[m*1024 + d]);
    float s2 = siluf(hs0[m*1024 + 512 + d]);
    sx[i] = s1; sz[i] = s2;
    int mf = (b << 9) + (LSEQ-1 - tt);
    fx[mf*DFF + d] = siluf(s1);
    fz[mf*DFF + d] = siluf(s2);
}

// ---------------------------------------------------------------------------
// Selective scan over nseq sequences of length LSEQ. Thread per (seq,d,n).
// ---------------------------------------------------------------------------
__global__ void scan_k(const float* __restrict__ delta, const float* __restrict__ u,
                       const float* __restrict__ Bm, int ldb,
                       const float* __restrict__ Alog,
                       float* __restrict__ hsum, int D, int nseq)
{
    int tid = blockIdx.x*256 + threadIdx.x;
    int n = tid & 15;
    int seg = tid >> 4;
    int d = seg % D;
    int s = seg / D;
    if (s >= nseq) return;
    float An = -expf(Alog[n]);
    float h = 0.f;
    int base = s * LSEQ;
    #pragma unroll 4
    for (int ts = 0; ts < LSEQ; ts++) {
        int r = base + ts;
        float dl = delta[r*D + d];
        float ul = u[r*D + d];
        float Bv = Bm[(long long)r*ldb + n];
        float a = expf(dl * An);
        h = fmaf(a, h, dl * ul * Bv);
        float v = h;
        v += __shfl_xor_sync(0xffffffffu, v, 1);
        v += __shfl_xor_sync(0xffffffffu, v, 2);
        v += __shfl_xor_sync(0xffffffffu, v, 4);
        v += __shfl_xor_sync(0xffffffffu, v, 8);
        if (n == 0) hsum[r*D + d] = v;
    }
}

// ---------------------------------------------------------------------------
// attn[s,i,j] = softmax_j( dot(q[s,i,:], k[s,j,:]) / 16 ).  Block per (i,s).
// ---------------------------------------------------------------------------
__global__ void attn_k(const float* __restrict__ q, const float* __restrict__ k,
                       float* __restrict__ attn)
{
    const int i = blockIdx.x, s = blockIdx.y;
    __shared__ float qs[16];
    __shared__ float red[16];
    const int t = threadIdx.x;  // 256
    if (t < 16) qs[t] = q[(s*LSEQ + i)*16 + t];
    __syncthreads();
    float v[2];
    #pragma unroll
    for (int jj = 0; jj < 2; jj++) {
        int j = t + jj*256;
        const float4* kr = (const float4*)(k + (long long)(s*LSEQ + j)*16);
        float4 k0 = kr[0], k1 = kr[1], k2 = kr[2], k3 = kr[3];
        float sc = qs[0]*k0.x + qs[1]*k0.y + qs[2]*k0.z + qs[3]*k0.w
                 + qs[4]*k1.x + qs[5]*k1.y + qs[6]*k1.z + qs[7]*k1.w
                 + qs[8]*k2.x + qs[9]*k2.y + qs[10]*k2.z + qs[11]*k2.w
                 + qs[12]*k3.x + qs[13]*k3.y + qs[14]*k3.z + qs[15]*k3.w;
        v[jj] = sc * (1.0f/16.0f);
    }
    float m = fmaxf(v[0], v[1]);
    for (int o=16;o;o>>=1) m = fmaxf(m, __shfl_xor_sync(0xffffffffu, m, o));
    if ((t&31)==0) red[t>>5] = m;
    __syncthreads();
    if (t == 0) { float mm = red[0]; for (int w=1;w<8;w++) mm = fmaxf(mm, red[w]); red[0] = mm; }
    __syncthreads();
    float bm = red[0];
    v[0] = expf(v[0]-bm); v[1] = expf(v[1]-bm);
    float sm = v[0] + v[1];
    for (int o=16;o;o>>=1) sm += __shfl_xor_sync(0xffffffffu, sm, o);
    if ((t&31)==0) red[8 + (t>>5)] = sm;
    __syncthreads();
    if (t == 0) { float ss = 0.f; for (int w=0;w<8;w++) ss += red[8+w]; red[8] = ss; }
    __syncthreads();
    float inv = 1.0f / red[8];
    float* arow = attn + ((long long)s*LSEQ + i)*LSEQ;
    arow[t]     = v[0]*inv;
    arow[t+256] = v[1]*inv;
}

// y[m, d] += Dm[m, d] * u[m, d]  over M2 rows (Dm = dbcd col 64+)
__global__ void addmul_k(float* __restrict__ y, const float* __restrict__ dbcd,
                         int ldp, const float* __restrict__ u, int D, int M2)
{
    int i = blockIdx.x*256 + threadIdx.x;
    if (i >= M2*D) return;
    int m = i / D, d = i - m*D;
    y[i] += dbcd[(long long)m*ldp + 64 + d] * u[i];
}

// dst[b, t, :] = src[b, L-1-t, :]   (2048 rows)
__global__ void flip_k(const float* __restrict__ src, float* __restrict__ dst, int D)
{
    int i = blockIdx.x*256 + threadIdx.x;
    if (i >= MR*D) return;
    int d = i % D; int m = i / D;
    int b = m >> 9, tt = m & (LSEQ-1);
    dst[((b<<9) + (LSEQ-1 - tt))*D + d] = src[i];
}

__global__ void addv_k(float* __restrict__ a, const float* __restrict__ b, int n)
{
    int i = blockIdx.x*256 + threadIdx.x;
    if (i < n) a[i] += b[i];
}

__global__ void silu_out_k(const float* __restrict__ x, float* __restrict__ out, int n)
{
    int i = blockIdx.x*256 + threadIdx.x;
    if (i < n) out[i] = siluf(x[i]);
}

// ---------------------------------------------------------------------------
// Host side
// ---------------------------------------------------------------------------
static inline void gemm(int act, int accf, const float* A, const float* W, const float* bias,
                        float* C, int M, int N, int K, int lda, int ldw, int ldc,
                        int bat = 1, long long Ab = 0, long long Wb = 0, long long Cb = 0)
{
    dim3 g((N + 63) / 64, M / 128, bat), b(256);
    if (accf) {
        gemm_k<0,1><<<g, b>>>(A, W, bias, C, M, N, K, lda, ldw, ldc, Ab, Wb, Cb);
    } else if (act == 0) {
        gemm_k<0,0><<<g, b>>>(A, W, bias, C, M, N, K, lda, ldw, ldc, Ab, Wb, Cb);
    } else {
        gemm_k<2,0><<<g, b>>>(A, W, bias, C, M, N, K, lda, ldw, ldc, Ab, Wb, Cb);
    }
}

// Merged-pair SSM: u is [4096 x D] (two stacked 2048-row problems sharing weights).
static void ssm_run2(const float* u, int D, const float* projw, int Np,
                     const float* dtw, const float* dtb, const float* Alog,
                     const float* qw, const float* qb, const float* kw, const float* kb,
                     bool useD, float* yout,
                     float* dbcd, float* delta, float* hsum, float* qbuf, float* kbuf,
                     float* attn)
{
    gemm(0, 0, u, projw, nullptr, dbcd, MR2, Np, D, D, Np, Np);
    gemm(2, 0, dbcd, dtw, dtb, delta, MR2, D, 32, Np, D, D);          // softplus
    scan_k<<<(8*D*16)/256, 256>>>(delta, u, dbcd + 32, Np, Alog, hsum, D, 8);
    gemm(2, 0, u, qw, qb, qbuf, MR2, 16, D, D, 16, 16);               // softplus
    gemm(2, 0, dbcd + 48, kw, kb, kbuf, MR2, 16, 16, Np, 16, 16);     // softplus
    attn_k<<<dim3(LSEQ, 8), 256>>>(qbuf, kbuf, attn);
    gemm(0, 0, attn, hsum, nullptr, yout, LSEQ, D, LSEQ, LSEQ, D, D,
         8, (long long)LSEQ*LSEQ, (long long)LSEQ*D, (long long)LSEQ*D);
    if (useD) addmul_k<<<(MR2*D)/256, 256>>>(yout, dbcd, Np, u, D, MR2);
}

extern "C" void kernel_launch(void* const* d_in, const int* in_sizes, int n_in,
                              void* d_out, int out_size)
{
    (void)in_sizes; (void)n_in; (void)out_size;
    float* S = nullptr;
    cudaGetSymbolAddress((void**)&S, g_scratch);

    // scratch layout (floats)
    float* hs0   = S;                 // 2048*1024
    float* usx   = hs0   + 2097152;   // [4096 x 512]  (sx rows 0..2047, sz rows 2048..)
    float* ufb   = usx   + 2097152;   // [4096 x 512]  (fx, fz)
    float* ub    = ufb   + 2097152;   // [4096 x 256]  (ub1, ub2)
    float* dbcd  = ub    + 1048576;   // 4096*576
    float* delta = dbcd  + 2359296;   // 4096*512
    float* hsum  = delta + 2097152;   // 4096*512
    float* qbuf  = hsum  + 2097152;   // 4096*16
    float* kbuf  = qbuf  + 65536;
    float* attn  = kbuf  + 65536;     // 8*512*512
    float* yfwd  = attn  + 2097152;   // [4096 x 512]
    float* ybwd  = yfwd  + 2097152;   // [4096 x 256]
    float* cat2  = ybwd  + 1048576;   // 2048*1024
    float* oe    = cat2  + 2097152;   // 2048*256
    float* oef   = oe    + 524288;    // 2048*256
    float* xbuf  = oef   + 524288;    // 2048*512

    const float* x             = (const float*)d_in[0];
    const float* in_w          = (const float*)d_in[1];
    const float* in_b          = (const float*)d_in[2];
    const float* x_proj_w      = (const float*)d_in[3];
    const float* dt_w          = (const float*)d_in[4];
    const float* dt_b          = (const float*)d_in[5];
    const float* A_log         = (const float*)d_in[6];
    const float* exit_x_w      = (const float*)d_in[7];
    const float* exit_x_b      = (const float*)d_in[8];
    const float* exit_z_w      = (const float*)d_in[9];
    const float* exit_z_b      = (const float*)d_in[10];
    const float* x_proj_exit_w = (const float*)d_in[11];
    const float* dt_exit_w     = (const float*)d_in[12];
    const float* dt_exit_b     = (const float*)d_in[13];
    const float* A_log_exit    = (const float*)d_in[14];
    const float* out_inner_w   = (const float*)d_in[15];
    const float* out_inner_b   = (const float*)d_in[16];
    const float* out_exit_w    = (const float*)d_in[17];
    const float* out_exit_b    = (const float*)d_in[18];
    const float* up_w          = (const float*)d_in[19];
    const float* up_b          = (const float*)d_in[20];
    const float* out_w         = (const float*)d_in[21];
    const float* out_b         = (const float*)d_in[22];
    const float* q_in_w        = (const float*)d_in[23];
    const float* q_in_b        = (const float*)d_in[24];
    const float* k_in_w        = (const float*)d_in[25];
    const float* k_in_b        = (const float*)d_in[26];
    const float* q_ex_w        = (const float*)d_in[27];
    const float* q_ex_b        = (const float*)d_in[28];
    const float* k_ex_w        = (const float*)d_in[29];
    const float* k_ex_b        = (const float*)d_in[30];

    const float* cur = x;
    for (int l = 0; l < 2; l++) {
        const float* in_w_l = in_w + (long long)l*512*1024;
        const float* in_b_l = in_b + l*1024;
        const float* xp_l   = x_proj_w + (long long)l*512*576;
        const float* dtw_l  = dt_w + l*32*512;
        const float* dtb_l  = dt_b + l*512;
        const float* Al_l   = A_log + l*16;
        const float* exw_l  = exit_x_w + (long long)l*512*256;
        const float* exb_l  = exit_x_b + l*256;
        const float* ezw_l  = exit_z_w + (long long)l*512*256;
        const float* ezb_l  = exit_z_b + l*256;
        const float* xpe_l  = x_proj_exit_w + (long long)l*256*320;
        const float* dtew_l = dt_exit_w + l*32*256;
        const float* dteb_l = dt_exit_b + l*256;
        const float* Ale_l  = A_log_exit + l*16;
        const float* oiw_l  = out_inner_w + (long long)l*1024*512;
        const float* oib_l  = out_inner_b + l*512;
        const float* oew_l  = out_exit_w + (long long)l*512*256;
        const float* oeb_l  = out_exit_b + l*256;
        const float* upw_l  = up_w + (long long)l*256*512;
        const float* upb_l  = up_b + l*512;
        const float* ow_l   = out_w + (long long)l*1024*512;
        const float* ob_l   = out_b + l*512;
        const float* qiw_l  = q_in_w + l*512*16;
        const float* qib_l  = q_in_b + l*16;
        const float* kiw_l  = k_in_w + l*16*16;
        const float* kib_l  = k_in_b + l*16;
        const float* qew_l  = q_ex_w + l*256*16;
        const float* qeb_l  = q_ex_b + l*16;
        const float* kew_l  = k_ex_w + l*16*16;
        const float* keb_l  = k_ex_b + l*16;

        // 1. hs0 = x @ in_w + in_b   (2048 x 1024)
        gemm(0, 0, cur, in_w_l, in_b_l, hs0, MR, 1024, 512, 512, 1024, 1024);
        // 2. activations + flipped inputs (contiguous stacked pairs)
        silu_flip_k<<<(MR*DFF)/256, 256>>>(hs0, usx, usx + MR*DFF, ufb, ufb + MR*DFF);
        // 3. backward-path inputs: ub = [fx@exw+b ; fz@ezw+b]
        gemm(0, 0, ufb,          exw_l, exb_l, ub,            MR, 256, 512, 512, 256, 256);
        gemm(0, 0, ufb + MR*DFF, ezw_l, ezb_l, ub + MR*256,   MR, 256, 512, 512, 256, 256);
        // 4. merged SSM pairs
        ssm_run2(usx, 512, xp_l,  576, dtw_l,  dtb_l,  Al_l,  qiw_l, qib_l, kiw_l, kib_l,
                 true,  yfwd, dbcd, delta, hsum, qbuf, kbuf, attn);
        ssm_run2(ub,  256, xpe_l, 320, dtew_l, dteb_l, Ale_l, qew_l, qeb_l, kew_l, keb_l,
                 false, ybwd, dbcd, delta, hsum, qbuf, kbuf, attn);
        // 5. out_inner via split-K accumulate: cat2[:,0:512] = y1f@Wtop + y2f@Wbot + b
        gemm(0, 0, yfwd,           oiw_l,           oib_l,   cat2, MR, 512, 512, 512, 512, 1024);
        gemm(0, 1, yfwd + MR*512,  oiw_l + 512*512, nullptr, cat2, MR, 512, 512, 512, 512, 1024);
        // out_exit: oe = y1b@Wtop + y2b@Wbot + b
        gemm(0, 0, ybwd,           oew_l,           oeb_l,   oe,   MR, 256, 256, 256, 256, 256);
        gemm(0, 1, ybwd + MR*256,  oew_l + 256*256, nullptr, oe,   MR, 256, 256, 256, 256, 256);
        flip_k<<<(MR*256)/256, 256>>>(oe, oef, 256);
        gemm(0, 0, oef, upw_l, upb_l, cat2 + 512, MR, 512, 256, 256, 512, 1024);
        // 6. residual + final projection
        addv_k<<<(MR*1024)/256, 256>>>(cat2, hs0, MR*1024);
        gemm(0, 0, cat2, ow_l, ob_l, xbuf, MR, 512, 1024, 1024, 512, 512);
        cur = xbuf;
    }
    silu_out_k<<<(MR*DMODEL)/256, 256>>>(xbuf, (float*)d_out, MR*DMODEL);
}

// round 3
// speedup vs baseline: 1.8934x; 1.3026x over previous
#include <cuda_runtime.h>
#include <math.h>
#include <stdint.h>

#define BATCH 4
#define LSEQ  512
#define DMODEL 512
#define DFF   512
#define DINNER 256
#define MR    (BATCH*LSEQ)   /* 2048 rows */
#define MR2   (2*MR)         /* 4096 rows: merged pair */

// ---------------------------------------------------------------------------
// Scratch: single static device buffer (allocation-free rule).  ~104 MB.
// ---------------------------------------------------------------------------
__device__ __align__(16) float g_scratch[26u*1024u*1024u];

__device__ __forceinline__ float siluf(float x){ return x / (1.0f + expf(-x)); }
__device__ __forceinline__ float softplusf(float x){ return (x > 20.0f) ? x : log1pf(expf(x)); }

__device__ __forceinline__ uint32_t f2tf32(float x){
    uint32_t r; asm("cvt.rna.tf32.f32 %0, %1;" : "=r"(r) : "f"(x)); return r;
}
__device__ __forceinline__ void mma_tf32(float* c, const uint32_t* a, const uint32_t* b){
    asm volatile("mma.sync.aligned.m16n8k8.row.col.f32.tf32.tf32.f32 "
        "{%0,%1,%2,%3}, {%4,%5,%6,%7}, {%8,%9}, {%0,%1,%2,%3};"
        : "+f"(c[0]),"+f"(c[1]),"+f"(c[2]),"+f"(c[3])
        : "r"(a[0]),"r"(a[1]),"r"(a[2]),"r"(a[3]), "r"(b[0]),"r"(b[1]));
}

// ---------------------------------------------------------------------------
// TF32 tensor-core GEMM: C[M,N] = act(A[M,K](lda) @ W[K,N](ldw) + bias) [+C]
// 128x64 tile, 256 threads (8 warps, 4x2), warp tile 32x32 (2x4 m16n8k8).
// K-chunk 16, double-buffered smem with store-side tf32 conversion.
// Requires: M % 128 == 0, K % 16 == 0. N arbitrary. Batched via blockIdx.z.
// ---------------------------------------------------------------------------
template<int ACT, int ACC>
__global__ __launch_bounds__(256)
void gemm_tc(const float* __restrict__ A, const float* __restrict__ W,
             const float* __restrict__ bias, float* __restrict__ C,
             int M, int N, int K, int lda, int ldw, int ldc,
             long long Ab, long long Wb, long long Cb)
{
    __shared__ uint32_t As[2][128][20];   // [row][k], stride 20 -> conflict-free frags
    __shared__ uint32_t Bs[2][16][72];    // [k][n],  stride 72 -> conflict-free frags
    const int bz = blockIdx.z;
    A += (long long)bz * Ab;  W += (long long)bz * Wb;  C += (long long)bz * Cb;
    const int t = threadIdx.x;
    const int lane = t & 31, wid = t >> 5;
    const int wm = wid >> 1, wn = wid & 1;        // warp 32-row block, 32-col block
    const int gp = lane >> 2, tg = lane & 3;
    const int row0 = blockIdx.y * 128, col0 = blockIdx.x * 64;
    const int a_r = t >> 1, a_k = (t & 1) * 8;    // A: 8 floats (2 x float4) per thread
    const int b_k = t >> 4, b_n = (t & 15) * 4;   // W: 4 floats per thread

    float c[2][4][4] = {};
    float4 av0, av1, bv;

    // prefetch chunk 0
    {
        const float* ap = A + (long long)(row0 + a_r) * lda + a_k;
        av0 = *(const float4*)ap; av1 = *(const float4*)(ap + 4);
        int gn = col0 + b_n;
        const float* wp = W + (long long)b_k * ldw + gn;
        if (gn + 3 < N) bv = *(const float4*)wp;
        else {
            bv.x = (gn  <N)?wp[0]:0.f; bv.y = (gn+1<N)?wp[1]:0.f;
            bv.z = (gn+2<N)?wp[2]:0.f; bv.w = (gn+3<N)?wp[3]:0.f;
        }
    }

    int buf = 0;
    for (int kb = 0; kb < K; kb += 16) {
        uint32_t* as = &As[buf][a_r][a_k];
        as[0]=f2tf32(av0.x); as[1]=f2tf32(av0.y); as[2]=f2tf32(av0.z); as[3]=f2tf32(av0.w);
        as[4]=f2tf32(av1.x); as[5]=f2tf32(av1.y); as[6]=f2tf32(av1.z); as[7]=f2tf32(av1.w);
        uint32_t* bs = &Bs[buf][b_k][b_n];
        bs[0]=f2tf32(bv.x); bs[1]=f2tf32(bv.y); bs[2]=f2tf32(bv.z); bs[3]=f2tf32(bv.w);
        __syncthreads();
        if (kb + 16 < K) {
            const float* ap = A + (long long)(row0 + a_r) * lda + (kb + 16) + a_k;
            av0 = *(const float4*)ap; av1 = *(const float4*)(ap + 4);
            int gn = col0 + b_n;
            const float* wp = W + (long long)(kb + 16 + b_k) * ldw + gn;
            if (gn + 3 < N) bv = *(const float4*)wp;
            else {
                bv.x = (gn  <N)?wp[0]:0.f; bv.y = (gn+1<N)?wp[1]:0.f;
                bv.z = (gn+2<N)?wp[2]:0.f; bv.w = (gn+3<N)?wp[3]:0.f;
            }
        }
        #pragma unroll
        for (int ks = 0; ks < 2; ks++) {
            const int k0 = ks * 8;
            uint32_t a[2][4], b[4][2];
            #pragma unroll
            for (int mb = 0; mb < 2; mb++) {
                int r0 = wm*32 + mb*16 + gp;
                a[mb][0] = As[buf][r0  ][k0 + tg];
                a[mb][1] = As[buf][r0+8][k0 + tg];
                a[mb][2] = As[buf][r0  ][k0 + 4 + tg];
                a[mb][3] = As[buf][r0+8][k0 + 4 + tg];
            }
            #pragma unroll
            for (int nb = 0; nb < 4; nb++) {
                int cc = wn*32 + nb*8 + gp;
                b[nb][0] = Bs[buf][k0 + tg    ][cc];
                b[nb][1] = Bs[buf][k0 + 4 + tg][cc];
            }
            #pragma unroll
            for (int mb = 0; mb < 2; mb++)
                #pragma unroll
                for (int nb = 0; nb < 4; nb++)
                    mma_tf32(c[mb][nb], a[mb], b[nb]);
        }
        buf ^= 1;
    }

    #pragma unroll
    for (int mb = 0; mb < 2; mb++) {
        #pragma unroll
        for (int half = 0; half < 2; half++) {
            long long gr = row0 + wm*32 + mb*16 + gp + half*8;
            #pragma unroll
            for (int nb = 0; nb < 4; nb++) {
                #pragma unroll
                for (int j = 0; j < 2; j++) {
                    int gn = col0 + wn*32 + nb*8 + tg*2 + j;
                    if (gn < N) {
                        float v = c[mb][nb][half*2 + j];
                        if (bias) v += bias[gn];
                        if (ACT==2) v = softplusf(v);
                        if (ACC) v += C[gr*ldc + gn];
                        C[gr*ldc + gn] = v;
                    }
                }
            }
        }
    }
}

// ---------------------------------------------------------------------------
// hs0(2048x1024) -> sx=silu(x), sz=silu(z) stacked [4096x512],
// fx = silu(flip_L(sx)), fz = silu(flip_L(sz)) stacked [4096x512]
// ---------------------------------------------------------------------------
__global__ void silu_flip_k(const float* __restrict__ hs0, float* __restrict__ sx,
                            float* __restrict__ sz, float* __restrict__ fx,
                            float* __restrict__ fz)
{
    int i = blockIdx.x*256 + threadIdx.x;
    if (i >= MR*DFF) return;
    int d = i & (DFF-1);
    int m = i >> 9;
    int b = m >> 9, tt = m & (LSEQ-1);
    float s1 = siluf(hs0[m*1024 + d]);
    float s2 = siluf(hs0[m*1024 + 512 + d]);
    sx[i] = s1; sz[i] = s2;
    int mf = (b << 9) + (LSEQ-1 - tt);
    fx[mf*DFF + d] = siluf(s1);
    fz[mf*DFF + d] = siluf(s2);
}

// ---------------------------------------------------------------------------
// Selective scan over nseq sequences of length LSEQ. Thread per (seq,d,n).
// ---------------------------------------------------------------------------
__global__ void scan_k(const float* __restrict__ delta, const float* __restrict__ u,
                       const float* __restrict__ Bm, int ldb,
                       const float* __restrict__ Alog,
                       float* __restrict__ hsum, int D, int nseq)
{
    int tid = blockIdx.x*256 + threadIdx.x;
    int n = tid & 15;
    int seg = tid >> 4;
    int d = seg % D;
    int s = seg / D;
    if (s >= nseq) return;
    float An = -expf(Alog[n]);
    float h = 0.f;
    int base = s * LSEQ;
    #pragma unroll 4
    for (int ts = 0; ts < LSEQ; ts++) {
        int r = base + ts;
        float dl = delta[r*D + d];
        float ul = u[r*D + d];
        float Bv = Bm[(long long)r*ldb + n];
        float a = expf(dl * An);
        h = fmaf(a, h, dl * ul * Bv);
        float v = h;
        v += __shfl_xor_sync(0xffffffffu, v, 1);
        v += __shfl_xor_sync(0xffffffffu, v, 2);
        v += __shfl_xor_sync(0xffffffffu, v, 4);
        v += __shfl_xor_sync(0xffffffffu, v, 8);
        if (n == 0) hsum[r*D + d] = v;
    }
}

// ---------------------------------------------------------------------------
// attn[s,i,j] = softmax_j( dot(q[s,i,:], k[s,j,:]) / 16 ).  Block per (i,s).
// ---------------------------------------------------------------------------
__global__ void attn_k(const float* __restrict__ q, const float* __restrict__ k,
                       float* __restrict__ attn)
{
    const int i = blockIdx.x, s = blockIdx.y;
    __shared__ float qs[16];
    __shared__ float red[16];
    const int t = threadIdx.x;  // 256
    if (t < 16) qs[t] = q[(s*LSEQ + i)*16 + t];
    __syncthreads();
    float v[2];
    #pragma unroll
    for (int jj = 0; jj < 2; jj++) {
        int j = t + jj*256;
        const float4* kr = (const float4*)(k + (long long)(s*LSEQ + j)*16);
        float4 k0 = kr[0], k1 = kr[1], k2 = kr[2], k3 = kr[3];
        float sc = qs[0]*k0.x + qs[1]*k0.y + qs[2]*k0.z + qs[3]*k0.w
                 + qs[4]*k1.x + qs[5]*k1.y + qs[6]*k1.z + qs[7]*k1.w
                 + qs[8]*k2.x + qs[9]*k2.y + qs[10]*k2.z + qs[11]*k2.w
                 + qs[12]*k3.x + qs[13]*k3.y + qs[14]*k3.z + qs[15]*k3.w;
        v[jj] = sc * (1.0f/16.0f);
    }
    float m = fmaxf(v[0], v[1]);
    for (int o=16;o;o>>=1) m = fmaxf(m, __shfl_xor_sync(0xffffffffu, m, o));
    if ((t&31)==0) red[t>>5] = m;
    __syncthreads();
    if (t == 0) { float mm = red[0]; for (int w=1;w<8;w++) mm = fmaxf(mm, red[w]); red[0] = mm; }
    __syncthreads();
    float bm = red[0];
    v[0] = expf(v[0]-bm); v[1] = expf(v[1]-bm);
    float sm = v[0] + v[1];
    for (int o=16;o;o>>=1) sm += __shfl_xor_sync(0xffffffffu, sm, o);
    if ((t&31)==0) red[8 + (t>>5)] = sm;
    __syncthreads();
    if (t == 0) { float ss = 0.f; for (int w=0;w<8;w++) ss += red[8+w]; red[8] = ss; }
    __syncthreads();
    float inv = 1.0f / red[8];
    float* arow = attn + ((long long)s*LSEQ + i)*LSEQ;
    arow[t]     = v[0]*inv;
    arow[t+256] = v[1]*inv;
}

// y[m, d] += Dm[m, d] * u[m, d]  over M2 rows (Dm = dbcd col 64+)
__global__ void addmul_k(float* __restrict__ y, const float* __restrict__ dbcd,
                         int ldp, const float* __restrict__ u, int D, int M2)
{
    int i = blockIdx.x*256 + threadIdx.x;
    if (i >= M2*D) return;
    int m = i / D, d = i - m*D;
    y[i] += dbcd[(long long)m*ldp + 64 + d] * u[i];
}

// dst[b, t, :] = src[b, L-1-t, :]   (2048 rows)
__global__ void flip_k(const float* __restrict__ src, float* __restrict__ dst, int D)
{
    int i = blockIdx.x*256 + threadIdx.x;
    if (i >= MR*D) return;
    int d = i % D; int m = i / D;
    int b = m >> 9, tt = m & (LSEQ-1);
    dst[((b<<9) + (LSEQ-1 - tt))*D + d] = src[i];
}

__global__ void addv_k(float* __restrict__ a, const float* __restrict__ b, int n)
{
    int i = blockIdx.x*256 + threadIdx.x;
    if (i < n) a[i] += b[i];
}

__global__ void silu_out_k(const float* __restrict__ x, float* __restrict__ out, int n)
{
    int i = blockIdx.x*256 + threadIdx.x;
    if (i < n) out[i] = siluf(x[i]);
}

// ---------------------------------------------------------------------------
// Host side
// ---------------------------------------------------------------------------
static inline void gemm(int act, int accf, const float* A, const float* W, const float* bias,
                        float* C, int M, int N, int K, int lda, int ldw, int ldc,
                        int bat = 1, long long Ab = 0, long long Wb = 0, long long Cb = 0)
{
    dim3 g((N + 63) / 64, M / 128, bat), b(256);
    if (accf) {
        gemm_tc<0,1><<<g, b>>>(A, W, bias, C, M, N, K, lda, ldw, ldc, Ab, Wb, Cb);
    } else if (act == 0) {
        gemm_tc<0,0><<<g, b>>>(A, W, bias, C, M, N, K, lda, ldw, ldc, Ab, Wb, Cb);
    } else {
        gemm_tc<2,0><<<g, b>>>(A, W, bias, C, M, N, K, lda, ldw, ldc, Ab, Wb, Cb);
    }
}

// Merged-pair SSM: u is [4096 x D] (two stacked 2048-row problems sharing weights).
static void ssm_run2(const float* u, int D, const float* projw, int Np,
                     const float* dtw, const float* dtb, const float* Alog,
                     const float* qw, const float* qb, const float* kw, const float* kb,
                     bool useD, float* yout,
                     float* dbcd, float* delta, float* hsum, float* qbuf, float* kbuf,
                     float* attn)
{
    gemm(0, 0, u, projw, nullptr, dbcd, MR2, Np, D, D, Np, Np);
    gemm(2, 0, dbcd, dtw, dtb, delta, MR2, D, 32, Np, D, D);          // softplus
    scan_k<<<(8*D*16)/256, 256>>>(delta, u, dbcd + 32, Np, Alog, hsum, D, 8);
    gemm(2, 0, u, qw, qb, qbuf, MR2, 16, D, D, 16, 16);               // softplus
    gemm(2, 0, dbcd + 48, kw, kb, kbuf, MR2, 16, 16, Np, 16, 16);     // softplus
    attn_k<<<dim3(LSEQ, 8), 256>>>(qbuf, kbuf, attn);
    gemm(0, 0, attn, hsum, nullptr, yout, LSEQ, D, LSEQ, LSEQ, D, D,
         8, (long long)LSEQ*LSEQ, (long long)LSEQ*D, (long long)LSEQ*D);
    if (useD) addmul_k<<<(MR2*D)/256, 256>>>(yout, dbcd, Np, u, D, MR2);
}

extern "C" void kernel_launch(void* const* d_in, const int* in_sizes, int n_in,
                              void* d_out, int out_size)
{
    (void)in_sizes; (void)n_in; (void)out_size;
    float* S = nullptr;
    cudaGetSymbolAddress((void**)&S, g_scratch);

    // scratch layout (floats)
    float* hs0   = S;                 // 2048*1024
    float* usx   = hs0   + 2097152;   // [4096 x 512]
    float* ufb   = usx   + 2097152;   // [4096 x 512]
    float* ub    = ufb   + 2097152;   // [4096 x 256]
    float* dbcd  = ub    + 1048576;   // 4096*576
    float* delta = dbcd  + 2359296;   // 4096*512
    float* hsum  = delta + 2097152;   // 4096*512
    float* qbuf  = hsum  + 2097152;   // 4096*16
    float* kbuf  = qbuf  + 65536;
    float* attn  = kbuf  + 65536;     // 8*512*512
    float* yfwd  = attn  + 2097152;   // [4096 x 512]
    float* ybwd  = yfwd  + 2097152;   // [4096 x 256]
    float* cat2  = ybwd  + 1048576;   // 2048*1024
    float* oe    = cat2  + 2097152;   // 2048*256
    float* oef   = oe    + 524288;    // 2048*256
    float* xbuf  = oef   + 524288;    // 2048*512

    const float* x             = (const float*)d_in[0];
    const float* in_w          = (const float*)d_in[1];
    const float* in_b          = (const float*)d_in[2];
    const float* x_proj_w      = (const float*)d_in[3];
    const float* dt_w          = (const float*)d_in[4];
    const float* dt_b          = (const float*)d_in[5];
    const float* A_log         = (const float*)d_in[6];
    const float* exit_x_w      = (const float*)d_in[7];
    const float* exit_x_b      = (const float*)d_in[8];
    const float* exit_z_w      = (const float*)d_in[9];
    const float* exit_z_b      = (const float*)d_in[10];
    const float* x_proj_exit_w = (const float*)d_in[11];
    const float* dt_exit_w     = (const float*)d_in[12];
    const float* dt_exit_b     = (const float*)d_in[13];
    const float* A_log_exit    = (const float*)d_in[14];
    const float* out_inner_w   = (const float*)d_in[15];
    const float* out_inner_b   = (const float*)d_in[16];
    const float* out_exit_w    = (const float*)d_in[17];
    const float* out_exit_b    = (const float*)d_in[18];
    const float* up_w          = (const float*)d_in[19];
    const float* up_b          = (const float*)d_in[20];
    const float* out_w         = (const float*)d_in[21];
    const float* out_b         = (const float*)d_in[22];
    const float* q_in_w        = (const float*)d_in[23];
    const float* q_in_b        = (const float*)d_in[24];
    const float* k_in_w        = (const float*)d_in[25];
    const float* k_in_b        = (const float*)d_in[26];
    const float* q_ex_w        = (const float*)d_in[27];
    const float* q_ex_b        = (const float*)d_in[28];
    const float* k_ex_w        = (const float*)d_in[29];
    const float* k_ex_b        = (const float*)d_in[30];

    const float* cur = x;
    for (int l = 0; l < 2; l++) {
        const float* in_w_l = in_w + (long long)l*512*1024;
        const float* in_b_l = in_b + l*1024;
        const float* xp_l   = x_proj_w + (long long)l*512*576;
        const float* dtw_l  = dt_w + l*32*512;
        const float* dtb_l  = dt_b + l*512;
        const float* Al_l   = A_log + l*16;
        const float* exw_l  = exit_x_w + (long long)l*512*256;
        const float* exb_l  = exit_x_b + l*256;
        const float* ezw_l  = exit_z_w + (long long)l*512*256;
        const float* ezb_l  = exit_z_b + l*256;
        const float* xpe_l  = x_proj_exit_w + (long long)l*256*320;
        const float* dtew_l = dt_exit_w + l*32*256;
        const float* dteb_l = dt_exit_b + l*256;
        const float* Ale_l  = A_log_exit + l*16;
        const float* oiw_l  = out_inner_w + (long long)l*1024*512;
        const float* oib_l  = out_inner_b + l*512;
        const float* oew_l  = out_exit_w + (long long)l*512*256;
        const float* oeb_l  = out_exit_b + l*256;
        const float* upw_l  = up_w + (long long)l*256*512;
        const float* upb_l  = up_b + l*512;
        const float* ow_l   = out_w + (long long)l*1024*512;
        const float* ob_l   = out_b + l*512;
        const float* qiw_l  = q_in_w + l*512*16;
        const float* qib_l  = q_in_b + l*16;
        const float* kiw_l  = k_in_w + l*16*16;
        const float* kib_l  = k_in_b + l*16;
        const float* qew_l  = q_ex_w + l*256*16;
        const float* qeb_l  = q_ex_b + l*16;
        const float* kew_l  = k_ex_w + l*16*16;
        const float* keb_l  = k_ex_b + l*16;

        // 1. hs0 = x @ in_w + in_b   (2048 x 1024)
        gemm(0, 0, cur, in_w_l, in_b_l, hs0, MR, 1024, 512, 512, 1024, 1024);
        // 2. activations + flipped inputs (contiguous stacked pairs)
        silu_flip_k<<<(MR*DFF)/256, 256>>>(hs0, usx, usx + MR*DFF, ufb, ufb + MR*DFF);
        // 3. backward-path inputs: ub = [fx@exw+b ; fz@ezw+b]
        gemm(0, 0, ufb,          exw_l, exb_l, ub,            MR, 256, 512, 512, 256, 256);
        gemm(0, 0, ufb + MR*DFF, ezw_l, ezb_l, ub + MR*256,   MR, 256, 512, 512, 256, 256);
        // 4. merged SSM pairs
        ssm_run2(usx, 512, xp_l,  576, dtw_l,  dtb_l,  Al_l,  qiw_l, qib_l, kiw_l, kib_l,
                 true,  yfwd, dbcd, delta, hsum, qbuf, kbuf, attn);
        ssm_run2(ub,  256, xpe_l, 320, dtew_l, dteb_l, Ale_l, qew_l, qeb_l, kew_l, keb_l,
                 false, ybwd, dbcd, delta, hsum, qbuf, kbuf, attn);
        // 5. out_inner via split-K accumulate
        gemm(0, 0, yfwd,           oiw_l,           oib_l,   cat2, MR, 512, 512, 512, 512, 1024);
        gemm(0, 1, yfwd + MR*512,  oiw_l + 512*512, nullptr, cat2, MR, 512, 512, 512, 512, 1024);
        gemm(0, 0, ybwd,           oew_l,           oeb_l,   oe,   MR, 256, 256, 256, 256, 256);
        gemm(0, 1, ybwd + MR*256,  oew_l + 256*256, nullptr, oe,   MR, 256, 256, 256, 256, 256);
        flip_k<<<(MR*256)/256, 256>>>(oe, oef, 256);
        gemm(0, 0, oef, upw_l, upb_l, cat2 + 512, MR, 512, 256, 256, 512, 1024);
        // 6. residual + final projection
        addv_k<<<(MR*1024)/256, 256>>>(cat2, hs0, MR*1024);
        gemm(0, 0, cat2, ow_l, ob_l, xbuf, MR, 512, 1024, 1024, 512, 512);
        cur = xbuf;
    }
    silu_out_k<<<(MR*DMODEL)/256, 256>>>(xbuf, (float*)d_out, MR*DMODEL);
}